// round 12
// baseline (speedup 1.0000x reference)
#include <cuda_runtime.h>
#include <cstdint>
#include <math.h>

// Problem dims
#define BB 16
#define NN 64
#define DD 512
#define PP 64
#define QQ 16
#define CELL 1024   // PP*QQ

// Output offsets (flat concat of reference return tuple, fp32)
#define OFF_M     0LL
#define OFF_MP    67108864LL
#define OFF_Q     134217728LL
#define OFF_K     134742016LL
#define OFF_COS   135266304LL
#define OFF_ABN   135266320LL
#define OFF_ABDJ  135274512LL
#define OFF_CT    135798800LL
#define OFF_CS    135864336LL
#define OFF_CDBL  135929872LL
#define OFF_PHAT  135995408LL

// k_rest block ranges (waiters strictly after waitees)
#define NB_ABN     16
#define NB_BIASBAR 256
#define NB_TAIL    1024
#define NB_BQ      512
#define NB_PROJ    512
#define R1 (NB_ABN)                     // 16
#define R2 (R1 + NB_BIASBAR)            // 272
#define R3 (R2 + NB_TAIL)               // 1296
#define R4 (R3 + NB_BQ)                 // 1808
#define R5 (R4 + NB_PROJ)               // 2320

// Scratch (__device__ globals: allocation-free)
__device__ float g_bias_bar[NN * CELL];
__device__ float g_bqp[32 * DD * NN];
__device__ float g_bkp[32 * DD * NN];
__device__ int   g_f_abn;
__device__ int   g_f_biasbar;
__device__ int   g_f_bq;
__device__ int   g_done;

// ===========================================================================
// k_rest: ALL non-big work in one launch, flag-synchronized.
// ===========================================================================
__global__ void __launch_bounds__(256) k_rest(
        const float* __restrict__ a, const float* __restrict__ bvec,
        const float* __restrict__ c, const float* __restrict__ dctx,
        const float* __restrict__ alpha, const float* __restrict__ bias,
        const float* __restrict__ wq, const float* __restrict__ wk,
        const float* __restrict__ abd_w, const float* __restrict__ abd_b,
        const float* __restrict__ ctx_w, const float* __restrict__ ctx_b,
        const float* __restrict__ w1, const float* __restrict__ b1,
        const float* __restrict__ w_prob, const float* __restrict__ b_prob,
        float* __restrict__ out) {
    __shared__ float4 pool4[1664];          // 26.6 KB unioned pool
    float* pool = (float*)pool4;
    int bid = blockIdx.x;
    int t = threadIdx.x;

    if (bid < R1) {
        // ---- ABN: cos_ab + abn -> out. One block per b. ----
        int b = bid;
        float* ra = pool;
        float* rb = pool + 256;
        float* rab = pool + 512;
        float* s_cos = pool + 768;
        float sa = 0.f, sb = 0.f, sab = 0.f;
        for (int d = t; d < DD; d += 256) {
            float av = a[b * DD + d], bv = bvec[b * DD + d];
            sa += av * av; sb += bv * bv; sab += av * bv;
        }
        ra[t] = sa; rb[t] = sb; rab[t] = sab;
        __syncthreads();
        for (int s = 128; s > 0; s >>= 1) {
            if (t < s) { ra[t] += ra[t + s]; rb[t] += rb[t + s]; rab[t] += rab[t + s]; }
            __syncthreads();
        }
        if (t == 0) {
            float na = fmaxf(sqrtf(ra[0]), 1e-8f);
            float nb = fmaxf(sqrtf(rb[0]), 1e-8f);
            float cosv = rab[0] / (na * nb);
            s_cos[0] = cosv;
            out[OFF_COS + b] = cosv;
        }
        __syncthreads();
        float cosv = s_cos[0];
        for (int d = t; d < DD; d += 256) {
            out[OFF_ABN + (long long)b * DD + d] =
                tanhf(a[b * DD + d] * (1.f - cosv)) + tanhf(bvec[b * DD + d] * cosv);
        }
        __threadfence();
        __syncthreads();
        if (t == 0) atomicAdd(&g_f_abn, 1);

    } else if (bid < R2) {
        // ---- BIASBAR: bias_bar[i, c0..c0+255] = mean_j bias[i,j,c]. ----
        int id = bid - R1;                  // 0..255
        int i = id >> 2;
        int c0 = (id & 3) * 256;
        float s = 0.f;
        const float* base = bias + (size_t)i * NN * CELL + c0 + t;
#pragma unroll 8
        for (int j = 0; j < NN; j++) s += base[(size_t)j * CELL];
        g_bias_bar[i * CELL + c0 + t] = s * (1.f / NN);
        __threadfence();
        __syncthreads();
        if (t == 0) atomicAdd(&g_f_biasbar, 1);

    } else if (bid < R3) {
        // ---- TAIL: one (b,n). Waits f_abn, reads precomputed abn. ----
        int bn = bid - R2;                  // 0..1023
        int b = bn >> 6, n = bn & 63;
        float* s_ct   = pool;            // 64
        float* s_cs   = pool + 64;       // 64
        float* s_abdj = pool + 128;      // 512
        float* s_d    = pool + 640;      // 16
        float* red    = pool + 656;      // 256
        float* red2   = pool + 912;      // 256
        float* s_stat = pool + 1424;     // 2
        float* s_p    = pool + 1426;     // 2

        if (t == 0) {
            while (atomicAdd(&g_f_abn, 0) < NB_ABN) __nanosleep(32);
        }
        __syncthreads();
        __threadfence();

        if (t < QQ) s_d[t] = dctx[bn * QQ + t];
        float v = 0.f;
        if (t < 64) { v = 64.f * c[(size_t)bn * 64 + t]; s_ct[t] = v; }
        __syncthreads();
        if (t < 32) {
            float m = fmaxf(s_ct[t], s_ct[t + 32]);
#pragma unroll
            for (int o = 16; o > 0; o >>= 1) m = fmaxf(m, __shfl_xor_sync(0xffffffffu, m, o));
            if (t == 0) s_stat[0] = m;
        }
        __syncthreads();
        float e = 0.f;
        if (t < 64) e = expf(v - s_stat[0]);
        red[t] = (t < 64) ? e : 0.f;
        __syncthreads();
        if (t < 32) {
            float s = red[t] + red[t + 32];
#pragma unroll
            for (int o = 16; o > 0; o >>= 1) s += __shfl_xor_sync(0xffffffffu, s, o);
            if (t == 0) s_stat[1] = s;
        }
        __syncthreads();
        if (t < 64) {
            float ct = e / s_stat[1];
            s_ct[t] = ct;
            out[OFF_CT + (long long)bn * 64 + t] = ct;
        }
        __syncthreads();

        if (t < 64) {
            float acc = b1[n * 64 + t];
            const float* w1r = w1 + ((size_t)n * 64 + t) * 64;
#pragma unroll 8
            for (int p = 0; p < 64; p++) acc += s_ct[p] * w1r[p];
            float cs = fmaxf(acc, 0.f);
            s_cs[t] = cs;
            out[OFF_CS + (long long)bn * 64 + t] = cs;
        }
        for (int d = t; d < DD; d += 256) {
            float dp = ctx_b[d];
            const float* cw = ctx_w + d * QQ;
#pragma unroll
            for (int q = 0; q < QQ; q++) dp += s_d[q] * cw[q];
            float abn = out[OFF_ABN + (long long)b * DD + d];   // precomputed
            float val = tanhf(abd_w[n * DD + d] * abn * dp + abd_b[n * DD + d]);
            s_abdj[d] = val;
            out[OFF_ABDJ + (long long)bn * DD + d] = val;
        }
        __syncthreads();

        float l0 = 0.f, l1 = 0.f;
        const float* wp0 = w_prob + (size_t)(n * 2 + 0) * 576;
        const float* wp1 = w_prob + (size_t)(n * 2 + 1) * 576;
        for (int k = t; k < 576; k += 256) {
            float cb = (k < 64) ? s_cs[k] : s_abdj[k - 64];
            l0 += cb * wp0[k];
            l1 += cb * wp1[k];
        }
        red[t] = l0; red2[t] = l1;
        __syncthreads();
        for (int s = 128; s > 0; s >>= 1) {
            if (t < s) { red[t] += red[t + s]; red2[t] += red2[t + s]; }
            __syncthreads();
        }
        if (t == 0) {
            float L0 = red[0] + b_prob[n * 2 + 0];
            float L1 = red2[0] + b_prob[n * 2 + 1];
            float m = fmaxf(L0, L1);
            float e0 = expf(L0 - m), e1 = expf(L1 - m);
            float inv = 1.f / (e0 + e1);
            s_p[0] = e0 * inv; s_p[1] = e1 * inv;
            out[OFF_PHAT + (long long)bn * 2 + 0] = s_p[0];
            out[OFF_PHAT + (long long)bn * 2 + 1] = s_p[1];
        }
        __syncthreads();
        if (t < 64) {
            float cs = s_cs[t];
            out[OFF_CDBL + (long long)bn * 64 + t] = tanhf(s_p[0] * cs) + tanhf(s_p[1] * cs);
        }

    } else if (bid < R4) {
        // ---- BQ/BK partials: (dt=16, cb=32) chunks of 32 c. Waits f_biasbar. ----
        int id = bid - R3;
        int dt = id >> 5, cb = id & 31;
        int c0 = cb * 32;
        int tx = t & 15, ty = t >> 4;
        float* sbb = pool;            // 64 x 33
        float* swq = pool + 2112;     // 32 x 33
        float* swk = pool + 3168;     // 32 x 33

        if (t == 0) {
            while (atomicAdd(&g_f_biasbar, 0) < NB_BIASBAR) __nanosleep(64);
        }
        __syncthreads();
        __threadfence();

#pragma unroll
        for (int it = 0; it < 2; it++) {
            int idx = t + 256 * it;
            int n = idx >> 3, c4 = idx & 7;
            float4 v = *(const float4*)(g_bias_bar + n * CELL + c0 + c4 * 4);
            sbb[n * 33 + c4 * 4 + 0] = v.x; sbb[n * 33 + c4 * 4 + 1] = v.y;
            sbb[n * 33 + c4 * 4 + 2] = v.z; sbb[n * 33 + c4 * 4 + 3] = v.w;
        }
        {
            int r = t >> 3, c4 = t & 7;
            float4 q = *(const float4*)(wq + (size_t)(dt * 32 + r) * CELL + c0 + c4 * 4);
            float4 k = *(const float4*)(wk + (size_t)(dt * 32 + r) * CELL + c0 + c4 * 4);
            swq[r * 33 + c4 * 4 + 0] = q.x; swq[r * 33 + c4 * 4 + 1] = q.y;
            swq[r * 33 + c4 * 4 + 2] = q.z; swq[r * 33 + c4 * 4 + 3] = q.w;
            swk[r * 33 + c4 * 4 + 0] = k.x; swk[r * 33 + c4 * 4 + 1] = k.y;
            swk[r * 33 + c4 * 4 + 2] = k.z; swk[r * 33 + c4 * 4 + 3] = k.w;
        }
        __syncthreads();

        float accq[2][4] = {}, acck[2][4] = {};
        for (int cc = 0; cc < 32; cc++) {
            float aq[2], ak[2], bv[4];
#pragma unroll
            for (int i = 0; i < 2; i++) {
                aq[i] = swq[(ty * 2 + i) * 33 + cc];
                ak[i] = swk[(ty * 2 + i) * 33 + cc];
            }
#pragma unroll
            for (int j = 0; j < 4; j++) bv[j] = sbb[(tx * 4 + j) * 33 + cc];
#pragma unroll
            for (int i = 0; i < 2; i++)
#pragma unroll
                for (int j = 0; j < 4; j++) {
                    accq[i][j] += aq[i] * bv[j];
                    acck[i][j] += ak[i] * bv[j];
                }
        }
#pragma unroll
        for (int i = 0; i < 2; i++)
#pragma unroll
            for (int j = 0; j < 4; j++) {
                int d = dt * 32 + ty * 2 + i;
                int n = tx * 4 + j;
                g_bqp[(size_t)cb * (DD * NN) + d * 64 + n] = accq[i][j];
                g_bkp[(size_t)cb * (DD * NN) + d * 64 + n] = acck[i][j];
            }
        __threadfence();
        __syncthreads();
        if (t == 0) atomicAdd(&g_f_bq, 1);

    } else {
        // ---- PROJ: (dt=32 tiles of 16 d-rows, b=16). Waits f_bq. ----
        int id = bid - R4;                  // 0..511
        int dt = id >> 4, b = id & 15;
        int tx = t & 15, ty = t >> 4;
        float* sc     = pool;               // 64 x 65
        float* swq    = pool + 4160;        // 16 x 65
        float* swk    = pool + 5200;        // 16 x 65
        float* s_part = pool + 6240;        // 256
        float* s_dbar = pool + 6496;        // 16

        float ap = 1.f + alpha[0];
        float s3 = ap * ap * ap;
        float tb = ap * ap + ap + 1.f;

        if (t == 0) {
            while (atomicAdd(&g_f_bq, 0) < NB_BQ) __nanosleep(64);
        }

        {
            int q = t & 15, g = t >> 4;
            const float* dbase = dctx + (size_t)b * NN * QQ;
            float s = 0.f;
#pragma unroll
            for (int jj = 0; jj < 4; jj++) s += dbase[(g * 4 + jj) * QQ + q];
            s_part[t] = s;
            __syncthreads();
            if (t < 16) {
                float acc = 0.f;
#pragma unroll
                for (int gg = 0; gg < 16; gg++) acc += s_part[gg * 16 + t];
                s_dbar[t] = acc * (1.f / 64.f);
            }
        }
        __threadfence();

#pragma unroll
        for (int it = 0; it < 4; it++) {
            int idx = t + 256 * it;
            int rr = idx >> 4, cv = idx & 15;
            float4 v = *(const float4*)(c + (size_t)(b * NN + rr) * PP + cv * 4);
            sc[rr * 65 + cv * 4 + 0] = v.x; sc[rr * 65 + cv * 4 + 1] = v.y;
            sc[rr * 65 + cv * 4 + 2] = v.z; sc[rr * 65 + cv * 4 + 3] = v.w;
        }
        __syncthreads();

#pragma unroll
        for (int it = 0; it < 4; it++) {
            int idx = t + 256 * it;
            int rr = idx >> 6, p = idx & 63;
            const float* wqr = wq + (size_t)(dt * 16 + rr) * CELL + p * 16;
            const float* wkr = wk + (size_t)(dt * 16 + rr) * CELL + p * 16;
            float sq = 0.f, sk = 0.f;
#pragma unroll
            for (int q = 0; q < 16; q++) {
                float dv = s_dbar[q];
                sq += dv * wqr[q];
                sk += dv * wkr[q];
            }
            swq[rr * 65 + p] = sq;
            swk[rr * 65 + p] = sk;
        }
        __syncthreads();

        float accq[4] = {}, acck[4] = {};
        for (int p = 0; p < PP; p++) {
            float aq = swq[ty * 65 + p];
            float ak = swk[ty * 65 + p];
#pragma unroll
            for (int j = 0; j < 4; j++) {
                float bv = sc[(tx * 4 + j) * 65 + p];
                accq[j] += aq * bv;
                acck[j] += ak * bv;
            }
        }
        int d = dt * 16 + ty;
        float4 bq4 = {0.f, 0.f, 0.f, 0.f};
        float4 bk4 = {0.f, 0.f, 0.f, 0.f};
#pragma unroll
        for (int cb = 0; cb < 32; cb++) {
            float4 vq = *(const float4*)(g_bqp + (size_t)cb * (DD * NN) + d * 64 + tx * 4);
            float4 vk = *(const float4*)(g_bkp + (size_t)cb * (DD * NN) + d * 64 + tx * 4);
            bq4.x += vq.x; bq4.y += vq.y; bq4.z += vq.z; bq4.w += vq.w;
            bk4.x += vk.x; bk4.y += vk.y; bk4.z += vk.z; bk4.w += vk.w;
        }
        float bqa[4] = {bq4.x, bq4.y, bq4.z, bq4.w};
        float bka[4] = {bk4.x, bk4.y, bk4.z, bk4.w};
#pragma unroll
        for (int j = 0; j < 4; j++) {
            int n = tx * 4 + j;
            long long o = (long long)b * (DD * NN) + d * NN + n;
            out[OFF_Q + o] = s3 * accq[j] + tb * bqa[j];
            out[OFF_K + o] = s3 * acck[j] + tb * bka[j];
        }
    }

    // Flag reset for graph replay: count ALL k_rest blocks.
    __syncthreads();
    if (t == 0) {
        int dn = atomicAdd(&g_done, 1);
        if (dn == R5 - 1) {
            g_f_abn = 0; g_f_biasbar = 0; g_f_bq = 0; g_done = 0;
            __threadfence();
        }
    }
}

// ===========================================================================
// k_big: the store kernel, EXACT r5 config (86.5us alone, 72% DRAM).
// ===========================================================================
__global__ void __launch_bounds__(256) k_big(
        const float* __restrict__ c, const float* __restrict__ dctx,
        const float* __restrict__ bias, const float* __restrict__ alpha,
        float* __restrict__ out) {
    int i  = blockIdx.x >> 4;    // 0..63
    int jc = blockIdx.x & 15;    // 0..15
    int j0 = jc * 4;
    int t = threadIdx.x;

    __shared__ float s_bias[4 * 1024];
    __shared__ float s_d[16 * 4 * 16];
    __shared__ float s_c[16 * 64];

    float ap = 1.f + alpha[0];
    float s3 = ap * ap * ap;
    float tb = ap * ap + ap + 1.f;

    {
        const float4* src = (const float4*)(bias + ((size_t)i * NN + j0) * CELL);
        float4* dst = (float4*)s_bias;
#pragma unroll
        for (int it = 0; it < 4; it++) dst[t + 256 * it] = src[t + 256 * it];
    }
    {
        int b = t >> 4, j = (t >> 2) & 3, qv = t & 3;
        ((float4*)s_d)[t] = *(const float4*)(dctx + ((size_t)b * NN + j0 + j) * QQ + qv * 4);
    }
    {
        int b = t >> 4, pv = t & 15;
        ((float4*)s_c)[t] = *(const float4*)(c + ((size_t)b * NN + i) * PP + pv * 4);
    }
    __syncthreads();

    int p = t >> 2;
    int qv = t & 3;
    float4* outbase = (float4*)out;
    const float4* sd4 = (const float4*)s_d;
    const float4* sb4 = (const float4*)s_bias;

    for (int b = 0; b < BB; b++) {
        float cv = s_c[b * 64 + p];
        size_t row = ((size_t)(b * NN + i) * NN + j0) * 256;
#pragma unroll
        for (int j = 0; j < 4; j++) {
            float4 d4 = sd4[(b * 4 + j) * 4 + qv];
            float4 bv = sb4[j * 256 + t];
            float4 mv;
            mv.x = cv * d4.x; mv.y = cv * d4.y; mv.z = cv * d4.z; mv.w = cv * d4.w;
            float4 mp;
            mp.x = s3 * mv.x + tb * bv.x;
            mp.y = s3 * mv.y + tb * bv.y;
            mp.z = s3 * mv.z + tb * bv.z;
            mp.w = s3 * mv.w + tb * bv.w;
            __stcs(&outbase[row + j * 256 + t], mv);
            __stcs(&outbase[(OFF_MP / 4) + row + j * 256 + t], mp);
        }
    }
}

// ---------------------------------------------------------------------------
extern "C" void kernel_launch(void* const* d_in, const int* in_sizes, int n_in,
                              void* d_out, int out_size) {
    const float* a      = (const float*)d_in[0];
    const float* b      = (const float*)d_in[1];
    const float* c      = (const float*)d_in[2];
    const float* dctx   = (const float*)d_in[3];
    const float* alpha  = (const float*)d_in[4];
    const float* bias   = (const float*)d_in[5];
    const float* wq     = (const float*)d_in[6];
    const float* wk     = (const float*)d_in[7];
    const float* abd_w  = (const float*)d_in[8];
    const float* abd_b  = (const float*)d_in[9];
    const float* ctx_w  = (const float*)d_in[10];
    const float* ctx_b  = (const float*)d_in[11];
    const float* w1     = (const float*)d_in[12];
    const float* b1     = (const float*)d_in[13];
    const float* w_prob = (const float*)d_in[14];
    const float* b_prob = (const float*)d_in[15];
    float* out = (float*)d_out;

    // Serial on one stream: k_rest alone (high occupancy, ~45-55us),
    // then k_big alone at its measured 86.5us DRAM-cap floor.
    k_rest<<<R5, 256>>>(a, b, c, dctx, alpha, bias, wq, wk,
                        abd_w, abd_b, ctx_w, ctx_b, w1, b1, w_prob, b_prob, out);
    k_big<<<1024, 256>>>(c, dctx, bias, alpha, out);
}

// round 14
// speedup vs baseline: 1.2306x; 1.2306x over previous
#include <cuda_runtime.h>
#include <cstdint>
#include <math.h>

// Problem dims
#define BB 16
#define NN 64
#define DD 512
#define PP 64
#define QQ 16
#define CELL 1024   // PP*QQ

// Output offsets (flat concat of reference return tuple, fp32)
#define OFF_M     0LL
#define OFF_MP    67108864LL
#define OFF_Q     134217728LL
#define OFF_K     134742016LL
#define OFF_COS   135266304LL
#define OFF_ABN   135266320LL
#define OFF_ABDJ  135274512LL
#define OFF_CT    135798800LL
#define OFF_CS    135864336LL
#define OFF_CDBL  135929872LL
#define OFF_PHAT  135995408LL

// Fused block ranges (waiters strictly after waitees in bid order)
#define NB_ABN     16
#define NB_BIASBAR 256
#define NB_TAIL    128     // 8 warps/block, warp-per-(b,n): 1024 units
#define NB_BQ      512
#define NB_BIG     1024
#define NB_PROJ    512
#define A1 (NB_ABN)                 // 16
#define A2 (A1 + NB_BIASBAR)        // 272
#define A3 (A2 + NB_TAIL)           // 400
#define A4 (A3 + NB_BQ)             // 912
#define A5 (A4 + NB_BIG)            // 1936
#define A6 (A5 + NB_PROJ)           // 2448

// Scratch (__device__ globals: allocation-free)
__device__ float g_bias_bar[NN * CELL];
__device__ float g_bqp[32 * DD * NN];
__device__ float g_bkp[32 * DD * NN];
__device__ int   g_f_abn;
__device__ int   g_f_biasbar;
__device__ int   g_f_bq;
__device__ int   g_done;

__global__ void __launch_bounds__(256) k_all(
        const float* __restrict__ a, const float* __restrict__ bvec,
        const float* __restrict__ c, const float* __restrict__ dctx,
        const float* __restrict__ alpha, const float* __restrict__ bias,
        const float* __restrict__ wq, const float* __restrict__ wk,
        const float* __restrict__ abd_w, const float* __restrict__ abd_b,
        const float* __restrict__ ctx_w, const float* __restrict__ ctx_b,
        const float* __restrict__ w1, const float* __restrict__ b1,
        const float* __restrict__ w_prob, const float* __restrict__ b_prob,
        float* __restrict__ out) {
    __shared__ float4 pool4[1664];          // 26.6 KB unioned pool
    float* pool = (float*)pool4;
    int bid = blockIdx.x;
    int t = threadIdx.x;

    if (bid < A1) {
        // ---- ABN: cos_ab + abn -> out. One block per b. ----
        int b = bid;
        float* ra = pool;
        float* rb = pool + 256;
        float* rab = pool + 512;
        float* s_cos = pool + 768;
        float sa = 0.f, sb = 0.f, sab = 0.f;
        for (int d = t; d < DD; d += 256) {
            float av = a[b * DD + d], bv = bvec[b * DD + d];
            sa += av * av; sb += bv * bv; sab += av * bv;
        }
        ra[t] = sa; rb[t] = sb; rab[t] = sab;
        __syncthreads();
        for (int s = 128; s > 0; s >>= 1) {
            if (t < s) { ra[t] += ra[t + s]; rb[t] += rb[t + s]; rab[t] += rab[t + s]; }
            __syncthreads();
        }
        if (t == 0) {
            float na = fmaxf(sqrtf(ra[0]), 1e-8f);
            float nb = fmaxf(sqrtf(rb[0]), 1e-8f);
            float cosv = rab[0] / (na * nb);
            s_cos[0] = cosv;
            out[OFF_COS + b] = cosv;
        }
        __syncthreads();
        float cosv = s_cos[0];
        for (int d = t; d < DD; d += 256) {
            out[OFF_ABN + (long long)b * DD + d] =
                tanhf(a[b * DD + d] * (1.f - cosv)) + tanhf(bvec[b * DD + d] * cosv);
        }
        __threadfence();
        __syncthreads();
        if (t == 0) atomicAdd(&g_f_abn, 1);

    } else if (bid < A2) {
        // ---- BIASBAR: bias_bar[i, c0..c0+255]. ----
        int id = bid - A1;                  // 0..255
        int i = id >> 2;
        int c0 = (id & 3) * 256;
        float s = 0.f;
        const float* base = bias + (size_t)i * NN * CELL + c0 + t;
#pragma unroll 8
        for (int j = 0; j < NN; j++) s += base[(size_t)j * CELL];
        g_bias_bar[i * CELL + c0 + t] = s * (1.f / NN);
        __threadfence();
        __syncthreads();
        if (t == 0) atomicAdd(&g_f_biasbar, 1);

    } else if (bid < A3) {
        // ---- TAIL: warp-per-(b,n). 8 warps/block; NO block barriers. ----
        int wid = t >> 5;                   // 0..7
        int l = t & 31;
        int bn = (bid - A2) * 8 + wid;      // 0..1023
        int b = bn >> 6, n = bn & 63;
        float* w = pool + wid * 672;        // 656 used, pad to 672
        float* w_d    = w;                  // 16
        float* w_ct   = w + 16;             // 64
        float* w_cs   = w + 80;             // 64
        float* w_abdj = w + 144;            // 512

        if (l == 0) {
            while (atomicAdd(&g_f_abn, 0) < NB_ABN) __nanosleep(32);
        }
        __syncwarp();

        if (l < QQ) w_d[l] = dctx[bn * QQ + l];
        __syncwarp();

        // softmax over 64 (2 per lane)
        float v0 = 64.f * c[(size_t)bn * 64 + l];
        float v1 = 64.f * c[(size_t)bn * 64 + l + 32];
        float m = fmaxf(v0, v1);
#pragma unroll
        for (int o = 16; o > 0; o >>= 1) m = fmaxf(m, __shfl_xor_sync(0xffffffffu, m, o));
        float e0 = expf(v0 - m), e1 = expf(v1 - m);
        float s = e0 + e1;
#pragma unroll
        for (int o = 16; o > 0; o >>= 1) s += __shfl_xor_sync(0xffffffffu, s, o);
        float inv = 1.f / s;
        float ct0 = e0 * inv, ct1 = e1 * inv;
        out[OFF_CT + (long long)bn * 64 + l] = ct0;
        out[OFF_CT + (long long)bn * 64 + l + 32] = ct1;
        w_ct[l] = ct0; w_ct[l + 32] = ct1;
        __syncwarp();

        // c_star: each lane outputs o=l and o=l+32
#pragma unroll
        for (int h = 0; h < 2; h++) {
            int o = l + h * 32;
            float acc = b1[n * 64 + o];
            const float* w1r = w1 + ((size_t)n * 64 + o) * 64;
#pragma unroll 8
            for (int p = 0; p < 64; p++) acc += w_ct[p] * w1r[p];
            float cs = fmaxf(acc, 0.f);
            w_cs[o] = cs;
            out[OFF_CS + (long long)bn * 64 + o] = cs;
        }

        // abdj: d = l, l+32, ... (16 per lane)
        for (int d = l; d < DD; d += 32) {
            float dp = ctx_b[d];
            const float* cw = ctx_w + d * QQ;
#pragma unroll
            for (int q = 0; q < QQ; q++) dp += w_d[q] * cw[q];
            float abn = out[OFF_ABN + (long long)b * DD + d];   // precomputed
            float val = tanhf(abd_w[n * DD + d] * abn * dp + abd_b[n * DD + d]);
            w_abdj[d] = val;
            out[OFF_ABDJ + (long long)bn * DD + d] = val;
        }
        __syncwarp();

        // logits over combined = [cs(64), abdj(512)]
        float l0 = 0.f, l1 = 0.f;
        const float* wp0 = w_prob + (size_t)(n * 2 + 0) * 576;
        const float* wp1 = w_prob + (size_t)(n * 2 + 1) * 576;
        for (int k = l; k < 576; k += 32) {
            float cb = (k < 64) ? w_cs[k] : w_abdj[k - 64];
            l0 += cb * wp0[k];
            l1 += cb * wp1[k];
        }
#pragma unroll
        for (int o = 16; o > 0; o >>= 1) {
            l0 += __shfl_xor_sync(0xffffffffu, l0, o);
            l1 += __shfl_xor_sync(0xffffffffu, l1, o);
        }
        float p0, p1;
        if (l == 0) {
            float L0 = l0 + b_prob[n * 2 + 0];
            float L1 = l1 + b_prob[n * 2 + 1];
            float mm = fmaxf(L0, L1);
            float q0 = expf(L0 - mm), q1 = expf(L1 - mm);
            float iv = 1.f / (q0 + q1);
            p0 = q0 * iv; p1 = q1 * iv;
            out[OFF_PHAT + (long long)bn * 2 + 0] = p0;
            out[OFF_PHAT + (long long)bn * 2 + 1] = p1;
        }
        p0 = __shfl_sync(0xffffffffu, p0, 0);
        p1 = __shfl_sync(0xffffffffu, p1, 0);
#pragma unroll
        for (int h = 0; h < 2; h++) {
            int o = l + h * 32;
            float cs = w_cs[o];
            out[OFF_CDBL + (long long)bn * 64 + o] = tanhf(p0 * cs) + tanhf(p1 * cs);
        }

    } else if (bid < A4) {
        // ---- BQ/BK partials: (dt=16, cb=32). Waits f_biasbar. ----
        int id = bid - A3;
        int dt = id >> 5, cb = id & 31;
        int c0 = cb * 32;
        int tx = t & 15, ty = t >> 4;
        float* sbb = pool;            // 64 x 33
        float* swq = pool + 2112;     // 32 x 33
        float* swk = pool + 3168;     // 32 x 33

        if (t == 0) {
            while (atomicAdd(&g_f_biasbar, 0) < NB_BIASBAR) __nanosleep(64);
        }
        __syncthreads();
        __threadfence();

#pragma unroll
        for (int it = 0; it < 2; it++) {
            int idx = t + 256 * it;
            int n = idx >> 3, c4 = idx & 7;
            float4 v = *(const float4*)(g_bias_bar + n * CELL + c0 + c4 * 4);
            sbb[n * 33 + c4 * 4 + 0] = v.x; sbb[n * 33 + c4 * 4 + 1] = v.y;
            sbb[n * 33 + c4 * 4 + 2] = v.z; sbb[n * 33 + c4 * 4 + 3] = v.w;
        }
        {
            int r = t >> 3, c4 = t & 7;
            float4 q = *(const float4*)(wq + (size_t)(dt * 32 + r) * CELL + c0 + c4 * 4);
            float4 k = *(const float4*)(wk + (size_t)(dt * 32 + r) * CELL + c0 + c4 * 4);
            swq[r * 33 + c4 * 4 + 0] = q.x; swq[r * 33 + c4 * 4 + 1] = q.y;
            swq[r * 33 + c4 * 4 + 2] = q.z; swq[r * 33 + c4 * 4 + 3] = q.w;
            swk[r * 33 + c4 * 4 + 0] = k.x; swk[r * 33 + c4 * 4 + 1] = k.y;
            swk[r * 33 + c4 * 4 + 2] = k.z; swk[r * 33 + c4 * 4 + 3] = k.w;
        }
        __syncthreads();

        float accq[2][4] = {}, acck[2][4] = {};
        for (int cc = 0; cc < 32; cc++) {
            float aq[2], ak[2], bv[4];
#pragma unroll
            for (int i = 0; i < 2; i++) {
                aq[i] = swq[(ty * 2 + i) * 33 + cc];
                ak[i] = swk[(ty * 2 + i) * 33 + cc];
            }
#pragma unroll
            for (int j = 0; j < 4; j++) bv[j] = sbb[(tx * 4 + j) * 33 + cc];
#pragma unroll
            for (int i = 0; i < 2; i++)
#pragma unroll
                for (int j = 0; j < 4; j++) {
                    accq[i][j] += aq[i] * bv[j];
                    acck[i][j] += ak[i] * bv[j];
                }
        }
#pragma unroll
        for (int i = 0; i < 2; i++)
#pragma unroll
            for (int j = 0; j < 4; j++) {
                int d = dt * 32 + ty * 2 + i;
                int n = tx * 4 + j;
                g_bqp[(size_t)cb * (DD * NN) + d * 64 + n] = accq[i][j];
                g_bkp[(size_t)cb * (DD * NN) + d * 64 + n] = acck[i][j];
            }
        __threadfence();
        __syncthreads();
        if (t == 0) atomicAdd(&g_f_bq, 1);

    } else if (bid < A5) {
        // ---- BIG: m and m_p for (i, j-chunk). Pure streaming, no waits. ----
        int id = bid - A4;                  // 0..1023
        int i  = id >> 4;
        int j0 = (id & 15) * 4;
        float* s_bias = pool;               // 4096
        float* s_d    = pool + 4096;        // 1024
        float* s_c    = pool + 5120;        // 1024

        float ap = 1.f + alpha[0];
        float s3 = ap * ap * ap;
        float tb = ap * ap + ap + 1.f;

        {
            const float4* src = (const float4*)(bias + ((size_t)i * NN + j0) * CELL);
            float4* dst = (float4*)s_bias;
#pragma unroll
            for (int it = 0; it < 4; it++) dst[t + 256 * it] = src[t + 256 * it];
        }
        {
            int b = t >> 4, j = (t >> 2) & 3, qv = t & 3;
            ((float4*)s_d)[t] = *(const float4*)(dctx + ((size_t)b * NN + j0 + j) * QQ + qv * 4);
        }
        {
            int b = t >> 4, pv = t & 15;
            ((float4*)s_c)[t] = *(const float4*)(c + ((size_t)b * NN + i) * PP + pv * 4);
        }
        __syncthreads();

        int p = t >> 2;
        int qv = t & 3;
        float4* outbase = (float4*)out;
        const float4* sd4 = (const float4*)s_d;
        const float4* sb4 = (const float4*)s_bias;

        for (int b = 0; b < BB; b++) {
            float cv = s_c[b * 64 + p];
            size_t row = ((size_t)(b * NN + i) * NN + j0) * 256;
#pragma unroll
            for (int j = 0; j < 4; j++) {
                float4 d4 = sd4[(b * 4 + j) * 4 + qv];
                float4 bv = sb4[j * 256 + t];
                float4 mv;
                mv.x = cv * d4.x; mv.y = cv * d4.y; mv.z = cv * d4.z; mv.w = cv * d4.w;
                float4 mp;
                mp.x = s3 * mv.x + tb * bv.x;
                mp.y = s3 * mv.y + tb * bv.y;
                mp.z = s3 * mv.z + tb * bv.z;
                mp.w = s3 * mv.w + tb * bv.w;
                __stcs(&outbase[row + j * 256 + t], mv);
                __stcs(&outbase[(OFF_MP / 4) + row + j * 256 + t], mp);
            }
        }

    } else {
        // ---- PROJ: (dt=32 tiles of 16 d-rows, b=16). Waits f_bq. ----
        int id = bid - A5;                  // 0..511
        int dt = id >> 4, b = id & 15;
        int tx = t & 15, ty = t >> 4;
        float* sc     = pool;               // 64 x 65
        float* swqp   = pool + 4160;        // 16 x 65
        float* swkp   = pool + 5200;        // 16 x 65
        float* s_part = pool + 6240;        // 256
        float* s_dbar = pool + 6496;        // 16

        float ap = 1.f + alpha[0];
        float s3 = ap * ap * ap;
        float tb = ap * ap + ap + 1.f;

        if (t == 0) {
            while (atomicAdd(&g_f_bq, 0) < NB_BQ) __nanosleep(64);
        }

        {
            int q = t & 15, g = t >> 4;
            const float* dbase = dctx + (size_t)b * NN * QQ;
            float s = 0.f;
#pragma unroll
            for (int jj = 0; jj < 4; jj++) s += dbase[(g * 4 + jj) * QQ + q];
            s_part[t] = s;
            __syncthreads();
            if (t < 16) {
                float acc = 0.f;
#pragma unroll
                for (int gg = 0; gg < 16; gg++) acc += s_part[gg * 16 + t];
                s_dbar[t] = acc * (1.f / 64.f);
            }
        }
        __threadfence();

#pragma unroll
        for (int it = 0; it < 4; it++) {
            int idx = t + 256 * it;
            int rr = idx >> 4, cv = idx & 15;
            float4 v = *(const float4*)(c + (size_t)(b * NN + rr) * PP + cv * 4);
            sc[rr * 65 + cv * 4 + 0] = v.x; sc[rr * 65 + cv * 4 + 1] = v.y;
            sc[rr * 65 + cv * 4 + 2] = v.z; sc[rr * 65 + cv * 4 + 3] = v.w;
        }
        __syncthreads();

#pragma unroll
        for (int it = 0; it < 4; it++) {
            int idx = t + 256 * it;
            int rr = idx >> 6, p = idx & 63;
            const float* wqr = wq + (size_t)(dt * 16 + rr) * CELL + p * 16;
            const float* wkr = wk + (size_t)(dt * 16 + rr) * CELL + p * 16;
            float sq = 0.f, sk = 0.f;
#pragma unroll
            for (int q = 0; q < 16; q++) {
                float dv = s_dbar[q];
                sq += dv * wqr[q];
                sk += dv * wkr[q];
            }
            swqp[rr * 65 + p] = sq;
            swkp[rr * 65 + p] = sk;
        }
        __syncthreads();

        float accq[4] = {}, acck[4] = {};
        for (int p = 0; p < PP; p++) {
            float aq = swqp[ty * 65 + p];
            float ak = swkp[ty * 65 + p];
#pragma unroll
            for (int j = 0; j < 4; j++) {
                float bv = sc[(tx * 4 + j) * 65 + p];
                accq[j] += aq * bv;
                acck[j] += ak * bv;
            }
        }
        int d = dt * 16 + ty;
        float4 bq4 = {0.f, 0.f, 0.f, 0.f};
        float4 bk4 = {0.f, 0.f, 0.f, 0.f};
#pragma unroll
        for (int cb = 0; cb < 32; cb++) {
            float4 vq = *(const float4*)(g_bqp + (size_t)cb * (DD * NN) + d * 64 + tx * 4);
            float4 vk = *(const float4*)(g_bkp + (size_t)cb * (DD * NN) + d * 64 + tx * 4);
            bq4.x += vq.x; bq4.y += vq.y; bq4.z += vq.z; bq4.w += vq.w;
            bk4.x += vk.x; bk4.y += vk.y; bk4.z += vk.z; bk4.w += vk.w;
        }
        float bqa[4] = {bq4.x, bq4.y, bq4.z, bq4.w};
        float bka[4] = {bk4.x, bk4.y, bk4.z, bk4.w};
#pragma unroll
        for (int j = 0; j < 4; j++) {
            int n = tx * 4 + j;
            long long o = (long long)b * (DD * NN) + d * NN + n;
            out[OFF_Q + o] = s3 * accq[j] + tb * bqa[j];
            out[OFF_K + o] = s3 * acck[j] + tb * bka[j];
        }
    }

    // Flag reset for graph replay: last of ALL blocks resets.
    __syncthreads();
    if (t == 0) {
        int dn = atomicAdd(&g_done, 1);
        if (dn == A6 - 1) {
            g_f_abn = 0; g_f_biasbar = 0; g_f_bq = 0; g_done = 0;
            __threadfence();
        }
    }
}

// ---------------------------------------------------------------------------
extern "C" void kernel_launch(void* const* d_in, const int* in_sizes, int n_in,
                              void* d_out, int out_size) {
    const float* a      = (const float*)d_in[0];
    const float* b      = (const float*)d_in[1];
    const float* c      = (const float*)d_in[2];
    const float* dctx   = (const float*)d_in[3];
    const float* alpha  = (const float*)d_in[4];
    const float* bias   = (const float*)d_in[5];
    const float* wq     = (const float*)d_in[6];
    const float* wk     = (const float*)d_in[7];
    const float* abd_w  = (const float*)d_in[8];
    const float* abd_b  = (const float*)d_in[9];
    const float* ctx_w  = (const float*)d_in[10];
    const float* ctx_b  = (const float*)d_in[11];
    const float* w1     = (const float*)d_in[12];
    const float* b1     = (const float*)d_in[13];
    const float* w_prob = (const float*)d_in[14];
    const float* b_prob = (const float*)d_in[15];
    float* out = (float*)d_out;

    k_all<<<A6, 256>>>(a, b, c, dctx, alpha, bias, wq, wk,
                       abd_w, abd_b, ctx_w, ctx_b, w1, b1, w_prob, b_prob, out);
}